// round 2
// baseline (speedup 1.0000x reference)
#include <cuda_runtime.h>
#include <cuda_bf16.h>
#include <cstdint>

// ---------------------------------------------------------------------------
// Problem constants
// ---------------------------------------------------------------------------
#define BB   16384
#define NE   32
#define EE   128
#define HH   256
#define TILE_M 128
#define TILES_PER_CTA 4
#define GROUPS 32                 // 32 groups * 4 tiles * 128 rows = 16384
#define NUM_CTAS (NE * GROUPS)

// SMEM pitches (bf16 elements)
#define PX  136
#define PW1 136
#define PW2 264

#define OFF_X   0
#define SZ_X    (TILE_M * PX * 2)             // 34816
#define OFF_W1  (OFF_X + SZ_X)
#define SZ_W1   (HH * PW1 * 2)                // 69632
#define OFF_W2  (OFF_W1 + SZ_W1)
#define SZ_W2   (EE * PW2 * 2)                // 67584
#define OFF_B1  (OFF_W2 + SZ_W2)
#define OFF_B2  (OFF_B1 + HH * 4)
#define OFF_RED (OFF_B2 + EE * 4)
#define SMEM_TOTAL (OFF_RED + 32 * 4)         // ~173.7 KB

// ---------------------------------------------------------------------------
// Base-ISA PTX helpers (NO 'a'-gated features: harness front-end is sm_103)
// ---------------------------------------------------------------------------
static __device__ __forceinline__ uint32_t smem_u32(const void* p) {
    uint32_t a;
    asm("{ .reg .u64 t; cvta.to.shared.u64 t, %1; cvt.u32.u64 %0, t; }"
        : "=r"(a) : "l"(p));
    return a;
}

#define LDSM4(r, addr)                                                        \
    asm volatile("ldmatrix.sync.aligned.m8n8.x4.shared.b16 {%0,%1,%2,%3}, [%4];" \
                 : "=r"((r)[0]), "=r"((r)[1]), "=r"((r)[2]), "=r"((r)[3])      \
                 : "r"(addr))

#define MMA16816(c, a, b0, b1)                                                \
    asm volatile(                                                             \
        "mma.sync.aligned.m16n8k16.row.col.f32.bf16.bf16.f32 "                \
        "{%0,%1,%2,%3},{%4,%5,%6,%7},{%8,%9},{%0,%1,%2,%3};"                  \
        : "+f"((c)[0]), "+f"((c)[1]), "+f"((c)[2]), "+f"((c)[3])              \
        : "r"((a)[0]), "r"((a)[1]), "r"((a)[2]), "r"((a)[3]),                 \
          "r"(b0), "r"(b1))

// ---------------------------------------------------------------------------
__device__ float g_partials[NUM_CTAS];

static __device__ __forceinline__ float gelu_exact(float x) {
    return 0.5f * x * (1.0f + erff(x * 0.70710678118654752f));
}

static __device__ __forceinline__ uint32_t packbf2(float lo, float hi) {
    __nv_bfloat162 p = __floats2bfloat162_rn(lo, hi);   // .x = lo (low 16 bits)
    return *reinterpret_cast<uint32_t*>(&p);
}

__global__ __launch_bounds__(256, 1)
void distill_kernel(const float* __restrict__ feat, const float* __restrict__ tgt,
                    const float* __restrict__ W1g, const float* __restrict__ b1g,
                    const float* __restrict__ W2g, const float* __restrict__ b2g) {
    extern __shared__ char smem[];
    const uint32_t sb  = smem_u32(smem);
    const int tid = threadIdx.x;
    const int wid = tid >> 5;
    const int lid = tid & 31;
    const int l4  = lid >> 2;           // fragment row within 8
    const int lc2 = (lid & 3) * 2;      // fragment col pair base
    const int n   = blockIdx.x;         // expert
    const int grp = blockIdx.y;         // 512-row group

    float* b1s = (float*)(smem + OFF_B1);
    float* b2s = (float*)(smem + OFF_B2);

    // ---- one-time: weights fp32 -> bf16, transposed into SMEM ----
    {
        const float* w1 = W1g + (size_t)n * EE * HH;     // [k=128][h=256]
        for (int f = tid; f < (EE * HH) / 4; f += 256) { // 8192 float4
            int k  = f >> 6;
            int h4 = (f & 63) * 4;
            float4 v = *(const float4*)(w1 + k * HH + h4);
            __nv_bfloat16* base = (__nv_bfloat16*)(smem + OFF_W1) + k;
            base[(size_t)(h4 + 0) * PW1] = __float2bfloat16(v.x);
            base[(size_t)(h4 + 1) * PW1] = __float2bfloat16(v.y);
            base[(size_t)(h4 + 2) * PW1] = __float2bfloat16(v.z);
            base[(size_t)(h4 + 3) * PW1] = __float2bfloat16(v.w);
        }
        const float* w2 = W2g + (size_t)n * HH * EE;     // [h=256][e=128]
        for (int f = tid; f < (HH * EE) / 4; f += 256) { // 8192 float4
            int h  = f >> 5;
            int e4 = (f & 31) * 4;
            float4 v = *(const float4*)(w2 + h * EE + e4);
            __nv_bfloat16* base = (__nv_bfloat16*)(smem + OFF_W2) + h;
            base[(size_t)(e4 + 0) * PW2] = __float2bfloat16(v.x);
            base[(size_t)(e4 + 1) * PW2] = __float2bfloat16(v.y);
            base[(size_t)(e4 + 2) * PW2] = __float2bfloat16(v.z);
            base[(size_t)(e4 + 3) * PW2] = __float2bfloat16(v.w);
        }
        b1s[tid] = b1g[n * HH + tid];
        if (tid < EE) b2s[tid] = b2g[n * EE + tid];
    }

    // per-lane ldmatrix address components
    const uint32_t xlane  = sb + OFF_X +
        (uint32_t)(((16 * wid + (lid & 15)) * PX + 8 * (lid >> 4)) * 2);
    const uint32_t w1lane = sb + OFF_W1 +
        (uint32_t)((((lid & 7) + 8 * (lid >> 4)) * PW1 + 8 * ((lid >> 3) & 1)) * 2);
    const uint32_t w2lane = sb + OFF_W2 +
        (uint32_t)((((lid & 7) + 8 * (lid >> 4)) * PW2 + 8 * ((lid >> 3) & 1)) * 2);

    float acc = 0.0f;

    for (int t = 0; t < TILES_PER_CTA; t++) {
        if (t) __syncthreads();          // previous tile done with X
        const int rowbase = grp * (TILES_PER_CTA * TILE_M) + t * TILE_M;

        // ---- stage X tile: fp32 GMEM -> bf16 SMEM (row-major, padded) ----
        for (int f = tid; f < (TILE_M * EE) / 4; f += 256) {   // 4096 float4
            int row  = f >> 5;
            int col4 = (f & 31) * 4;
            float4 v = *(const float4*)(feat +
                        ((size_t)(rowbase + row) * NE + n) * EE + col4);
            uint2 u;
            u.x = packbf2(v.x, v.y);
            u.y = packbf2(v.z, v.w);
            *reinterpret_cast<uint2*>(smem + OFF_X + (size_t)(row * PX + col4) * 2) = u;
        }
        __syncthreads();

        float c2[16][4];
        #pragma unroll
        for (int i = 0; i < 16; i++) { c2[i][0]=c2[i][1]=c2[i][2]=c2[i][3]=0.f; }

        #pragma unroll
        for (int half = 0; half < 2; half++) {
            // ---- GEMM1 half: C1[16 x 128] = X[16 x 128] * W1[:, half] ----
            float c1[16][4];
            #pragma unroll
            for (int i = 0; i < 16; i++) { c1[i][0]=c1[i][1]=c1[i][2]=c1[i][3]=0.f; }

            #pragma unroll
            for (int s = 0; s < 8; s++) {                 // k16 steps over E=128
                uint32_t a[4];
                LDSM4(a, xlane + (uint32_t)(16 * s * 2));
                #pragma unroll
                for (int jp = 0; jp < 8; jp++) {          // n16 pairs over 128 h-cols
                    uint32_t b[4];
                    LDSM4(b, w1lane + (uint32_t)(((half * 128 + 16 * jp) * PW1 + 16 * s) * 2));
                    MMA16816(c1[2 * jp],     a, b[0], b[1]);
                    MMA16816(c1[2 * jp + 1], a, b[2], b[3]);
                }
            }

            // ---- bias + exact GELU in registers -> GEMM2 A-fragments ----
            // C1 frag (row l/4, cols 8j+lc2+{0,1}; rows +8) == A frag layout.
            uint32_t A2[8][4];
            #pragma unroll
            for (int j = 0; j < 16; j++) {
                const float bb0 = b1s[half * 128 + 8 * j + lc2];
                const float bb1 = b1s[half * 128 + 8 * j + lc2 + 1];
                float v0 = gelu_exact(c1[j][0] + bb0);
                float v1 = gelu_exact(c1[j][1] + bb1);
                float v2 = gelu_exact(c1[j][2] + bb0);
                float v3 = gelu_exact(c1[j][3] + bb1);
                A2[j >> 1][(j & 1) * 2 + 0] = packbf2(v0, v1);
                A2[j >> 1][(j & 1) * 2 + 1] = packbf2(v2, v3);
            }

            // ---- GEMM2 partial: C2 += H_half[16 x 128] * W2[half block, :] ----
            #pragma unroll
            for (int s = 0; s < 8; s++) {                 // k16 steps over this half
                #pragma unroll
                for (int tp = 0; tp < 8; tp++) {          // e16 pairs over E=128
                    uint32_t b[4];
                    LDSM4(b, w2lane + (uint32_t)((16 * tp * PW2 + half * 128 + 16 * s) * 2));
                    MMA16816(c2[2 * tp],     A2[s], b[0], b[1]);
                    MMA16816(c2[2 * tp + 1], A2[s], b[2], b[3]);
                }
            }
        }

        // ---- MSE epilogue: targets read as exact fp32 from GMEM ----
        {
            const int r0 = rowbase + 16 * wid + l4;
            const float* tg0 = tgt + ((size_t)r0 * NE + n) * EE;
            const float* tg1 = tg0 + (size_t)8 * NE * EE;   // row + 8
            #pragma unroll
            for (int tp = 0; tp < 16; tp++) {
                const int e = 8 * tp + lc2;
                const float bb0 = b2s[e], bb1 = b2s[e + 1];
                float2 t0 = *(const float2*)(tg0 + e);
                float2 t1 = *(const float2*)(tg1 + e);
                float d0 = c2[tp][0] + bb0 - t0.x;
                float d1 = c2[tp][1] + bb1 - t0.y;
                float d2 = c2[tp][2] + bb0 - t1.x;
                float d3 = c2[tp][3] + bb1 - t1.y;
                acc += d0 * d0 + d1 * d1 + d2 * d2 + d3 * d3;
            }
        }
    }

    // ---- block reduction -> per-CTA partial ----
    #pragma unroll
    for (int o = 16; o > 0; o >>= 1) acc += __shfl_down_sync(0xffffffffu, acc, o);
    float* red = (float*)(smem + OFF_RED);
    __syncthreads();
    if (lid == 0) red[wid] = acc;
    __syncthreads();
    if (tid == 0) {
        float s = 0.f;
        #pragma unroll
        for (int i = 0; i < 8; i++) s += red[i];
        g_partials[blockIdx.y * NE + blockIdx.x] = s;
    }
}

__global__ void finalize_kernel(float* __restrict__ out) {
    const int tid = threadIdx.x;
    double s = 0.0;
    for (int i = tid; i < NUM_CTAS; i += 256) s += (double)g_partials[i];
    #pragma unroll
    for (int o = 16; o > 0; o >>= 1) s += __shfl_down_sync(0xffffffffu, s, o);
    __shared__ double sm[8];
    if ((tid & 31) == 0) sm[tid >> 5] = s;
    __syncthreads();
    if (tid == 0) {
        double tot = 0.0;
        #pragma unroll
        for (int i = 0; i < 8; i++) tot += sm[i];
        out[0] = (float)(tot * (1.0 / 67108864.0));   // / (B*NE*E)
    }
}

extern "C" void kernel_launch(void* const* d_in, const int* in_sizes, int n_in,
                              void* d_out, int out_size) {
    (void)in_sizes; (void)n_in; (void)out_size;
    const float* feat = (const float*)d_in[0];
    const float* tgt  = (const float*)d_in[1];
    const float* W1   = (const float*)d_in[2];
    const float* b1   = (const float*)d_in[3];
    const float* W2   = (const float*)d_in[4];
    const float* b2   = (const float*)d_in[5];

    cudaFuncSetAttribute(distill_kernel,
                         cudaFuncAttributeMaxDynamicSharedMemorySize, SMEM_TOTAL);
    dim3 grid(NE, GROUPS);
    distill_kernel<<<grid, 256, SMEM_TOTAL>>>(feat, tgt, W1, b1, W2, b2);
    finalize_kernel<<<1, 256>>>((float*)d_out);
}

// round 3
// speedup vs baseline: 1.3642x; 1.3642x over previous
#include <cuda_runtime.h>
#include <cuda_bf16.h>
#include <cstdint>

// ---------------------------------------------------------------------------
// Problem constants
// ---------------------------------------------------------------------------
#define BB   16384
#define NE   32
#define EE   128
#define HH   256
#define TILE_M 128
#define TILES_PER_CTA 4
#define GROUPS 32                 // 32 groups * 4 tiles * 128 rows = 16384
#define NUM_CTAS (NE * GROUPS)

// SMEM pitches (bf16 elements)
#define PX  136
#define PW1 136
#define PW2 264

#define OFF_X   0
#define SZ_X    (TILE_M * PX * 2)             // 34816
#define OFF_W1  (OFF_X + SZ_X)
#define SZ_W1   (HH * PW1 * 2)                // 69632
#define OFF_W2  (OFF_W1 + SZ_W1)
#define SZ_W2   (EE * PW2 * 2)                // 67584
#define OFF_B1  (OFF_W2 + SZ_W2)
#define OFF_B2  (OFF_B1 + HH * 4)
#define OFF_RED (OFF_B2 + EE * 4)
#define SMEM_TOTAL (OFF_RED + 32 * 4)         // ~173.7 KB

// ---------------------------------------------------------------------------
// Base-ISA PTX helpers (NO 'a'-gated features: harness front-end is sm_103)
// ---------------------------------------------------------------------------
static __device__ __forceinline__ uint32_t smem_u32(const void* p) {
    uint32_t a;
    asm("{ .reg .u64 t; cvta.to.shared.u64 t, %1; cvt.u32.u64 %0, t; }"
        : "=r"(a) : "l"(p));
    return a;
}

#define LDSM4(r, addr)                                                        \
    asm volatile("ldmatrix.sync.aligned.m8n8.x4.shared.b16 {%0,%1,%2,%3}, [%4];" \
                 : "=r"((r)[0]), "=r"((r)[1]), "=r"((r)[2]), "=r"((r)[3])      \
                 : "r"(addr))

#define MMA16816(c, a, b0, b1)                                                \
    asm volatile(                                                             \
        "mma.sync.aligned.m16n8k16.row.col.f32.bf16.bf16.f32 "                \
        "{%0,%1,%2,%3},{%4,%5,%6,%7},{%8,%9},{%0,%1,%2,%3};"                  \
        : "+f"((c)[0]), "+f"((c)[1]), "+f"((c)[2]), "+f"((c)[3])              \
        : "r"((a)[0]), "r"((a)[1]), "r"((a)[2]), "r"((a)[3]),                 \
          "r"(b0), "r"(b1))

// ---------------------------------------------------------------------------
static __device__ __forceinline__ float gelu_fast(float x) {
    // tanh-form GELU with HW tanh.approx (base PTX, sm_75+).
    // |gelu_tanh - gelu_erf| <= ~3e-4, MUFU tanh err ~5e-4 -> loss rel err ~1e-4.
    float u = x * (0.7978845608f + 0.0356774081f * x * x);
    float t;
    asm("tanh.approx.f32 %0, %1;" : "=f"(t) : "f"(u));
    return 0.5f * x * (1.0f + t);
}

static __device__ __forceinline__ uint32_t packbf2(float lo, float hi) {
    __nv_bfloat162 p = __floats2bfloat162_rn(lo, hi);   // .x = lo (low 16 bits)
    return *reinterpret_cast<uint32_t*>(&p);
}

__global__ void init_out_kernel(float* __restrict__ out) {
    out[0] = 0.0f;
}

__global__ __launch_bounds__(256, 1)
void distill_kernel(const float* __restrict__ feat, const float* __restrict__ tgt,
                    const float* __restrict__ W1g, const float* __restrict__ b1g,
                    const float* __restrict__ W2g, const float* __restrict__ b2g,
                    float* __restrict__ out) {
    extern __shared__ char smem[];
    const uint32_t sb  = smem_u32(smem);
    const int tid = threadIdx.x;
    const int wid = tid >> 5;
    const int lid = tid & 31;
    const int l4  = lid >> 2;           // fragment row within 8
    const int lc2 = (lid & 3) * 2;      // fragment col pair base
    const int n   = blockIdx.x;         // expert
    const int grp = blockIdx.y;         // 512-row group

    float* b1s = (float*)(smem + OFF_B1);
    float* b2s = (float*)(smem + OFF_B2);

    // ---- one-time: weights fp32 -> bf16, transposed into SMEM ----
    {
        const float* w1 = W1g + (size_t)n * EE * HH;     // [k=128][h=256]
        #pragma unroll 4
        for (int f = tid; f < (EE * HH) / 4; f += 256) { // 8192 float4
            int k  = f >> 6;
            int h4 = (f & 63) * 4;
            float4 v = *(const float4*)(w1 + k * HH + h4);
            __nv_bfloat16* base = (__nv_bfloat16*)(smem + OFF_W1) + k;
            base[(size_t)(h4 + 0) * PW1] = __float2bfloat16(v.x);
            base[(size_t)(h4 + 1) * PW1] = __float2bfloat16(v.y);
            base[(size_t)(h4 + 2) * PW1] = __float2bfloat16(v.z);
            base[(size_t)(h4 + 3) * PW1] = __float2bfloat16(v.w);
        }
        const float* w2 = W2g + (size_t)n * HH * EE;     // [h=256][e=128]
        #pragma unroll 4
        for (int f = tid; f < (HH * EE) / 4; f += 256) { // 8192 float4
            int h  = f >> 5;
            int e4 = (f & 31) * 4;
            float4 v = *(const float4*)(w2 + h * EE + e4);
            __nv_bfloat16* base = (__nv_bfloat16*)(smem + OFF_W2) + h;
            base[(size_t)(e4 + 0) * PW2] = __float2bfloat16(v.x);
            base[(size_t)(e4 + 1) * PW2] = __float2bfloat16(v.y);
            base[(size_t)(e4 + 2) * PW2] = __float2bfloat16(v.z);
            base[(size_t)(e4 + 3) * PW2] = __float2bfloat16(v.w);
        }
        b1s[tid] = b1g[n * HH + tid];
        if (tid < EE) b2s[tid] = b2g[n * EE + tid];
    }

    // per-lane ldmatrix address components
    const uint32_t xlane  = sb + OFF_X +
        (uint32_t)(((16 * wid + (lid & 15)) * PX + 8 * (lid >> 4)) * 2);
    const uint32_t w1lane = sb + OFF_W1 +
        (uint32_t)((((lid & 7) + 8 * (lid >> 4)) * PW1 + 8 * ((lid >> 3) & 1)) * 2);
    const uint32_t w2lane = sb + OFF_W2 +
        (uint32_t)((((lid & 7) + 8 * (lid >> 4)) * PW2 + 8 * ((lid >> 3) & 1)) * 2);

    float acc = 0.0f;

    for (int t = 0; t < TILES_PER_CTA; t++) {
        if (t) __syncthreads();          // previous tile done with X
        const int rowbase = grp * (TILES_PER_CTA * TILE_M) + t * TILE_M;

        // ---- stage X tile: fp32 GMEM -> bf16 SMEM. Fully unrolled so the 16
        // LDG.128 issue back-to-back (MLP ~16) instead of serializing DRAM
        // round trips. ----
        {
            const int row0  = tid >> 5;          // rows row0, row0+8, ..., +120
            const int col4  = (tid & 31) * 4;
            const float* gp = feat + ((size_t)(rowbase + row0) * NE + n) * EE + col4;
            char* sp = smem + OFF_X + (size_t)(row0 * PX + col4) * 2;
            #pragma unroll
            for (int it = 0; it < 16; it++) {
                float4 v = *(const float4*)(gp + (size_t)it * 8 * NE * EE);
                uint2 u;
                u.x = packbf2(v.x, v.y);
                u.y = packbf2(v.z, v.w);
                *reinterpret_cast<uint2*>(sp + (size_t)it * 8 * PX * 2) = u;
            }
        }
        __syncthreads();

        float c2[16][4];
        #pragma unroll
        for (int i = 0; i < 16; i++) { c2[i][0]=c2[i][1]=c2[i][2]=c2[i][3]=0.f; }

        #pragma unroll
        for (int half = 0; half < 2; half++) {
            // ---- GEMM1 half: C1[16 x 128] = X[16 x 128] * W1[:, half] ----
            float c1[16][4];
            #pragma unroll
            for (int i = 0; i < 16; i++) { c1[i][0]=c1[i][1]=c1[i][2]=c1[i][3]=0.f; }

            #pragma unroll
            for (int s = 0; s < 8; s++) {                 // k16 steps over E=128
                uint32_t a[4];
                LDSM4(a, xlane + (uint32_t)(16 * s * 2));
                #pragma unroll
                for (int jp = 0; jp < 8; jp++) {          // n16 pairs over 128 h-cols
                    uint32_t b[4];
                    LDSM4(b, w1lane + (uint32_t)(((half * 128 + 16 * jp) * PW1 + 16 * s) * 2));
                    MMA16816(c1[2 * jp],     a, b[0], b[1]);
                    MMA16816(c1[2 * jp + 1], a, b[2], b[3]);
                }
            }

            // ---- bias + fast GELU in registers -> GEMM2 A-fragments ----
            // C1 frag (row l/4, cols 8j+lc2+{0,1}; rows +8) == A frag layout.
            uint32_t A2[8][4];
            #pragma unroll
            for (int j = 0; j < 16; j++) {
                const float bb0 = b1s[half * 128 + 8 * j + lc2];
                const float bb1 = b1s[half * 128 + 8 * j + lc2 + 1];
                float v0 = gelu_fast(c1[j][0] + bb0);
                float v1 = gelu_fast(c1[j][1] + bb1);
                float v2 = gelu_fast(c1[j][2] + bb0);
                float v3 = gelu_fast(c1[j][3] + bb1);
                A2[j >> 1][(j & 1) * 2 + 0] = packbf2(v0, v1);
                A2[j >> 1][(j & 1) * 2 + 1] = packbf2(v2, v3);
            }

            // ---- GEMM2 partial: C2 += H_half[16 x 128] * W2[half block, :] ----
            #pragma unroll
            for (int s = 0; s < 8; s++) {                 // k16 steps over this half
                #pragma unroll
                for (int tp = 0; tp < 8; tp++) {          // e16 pairs over E=128
                    uint32_t b[4];
                    LDSM4(b, w2lane + (uint32_t)((16 * tp * PW2 + half * 128 + 16 * s) * 2));
                    MMA16816(c2[2 * tp],     A2[s], b[0], b[1]);
                    MMA16816(c2[2 * tp + 1], A2[s], b[2], b[3]);
                }
            }
        }

        // ---- MSE epilogue: targets read as exact fp32 from GMEM ----
        {
            const int r0 = rowbase + 16 * wid + l4;
            const float* tg0 = tgt + ((size_t)r0 * NE + n) * EE;
            const float* tg1 = tg0 + (size_t)8 * NE * EE;   // row + 8
            #pragma unroll
            for (int tp = 0; tp < 16; tp++) {
                const int e = 8 * tp + lc2;
                const float bb0 = b2s[e], bb1 = b2s[e + 1];
                float2 t0 = *(const float2*)(tg0 + e);
                float2 t1 = *(const float2*)(tg1 + e);
                float d0 = c2[tp][0] + bb0 - t0.x;
                float d1 = c2[tp][1] + bb1 - t0.y;
                float d2 = c2[tp][2] + bb0 - t1.x;
                float d3 = c2[tp][3] + bb1 - t1.y;
                acc += d0 * d0 + d1 * d1 + d2 * d2 + d3 * d3;
            }
        }
    }

    // ---- block reduction -> scaled atomic into d_out ----
    #pragma unroll
    for (int o = 16; o > 0; o >>= 1) acc += __shfl_down_sync(0xffffffffu, acc, o);
    float* red = (float*)(smem + OFF_RED);
    __syncthreads();
    if (lid == 0) red[wid] = acc;
    __syncthreads();
    if (tid == 0) {
        float s = 0.f;
        #pragma unroll
        for (int i = 0; i < 8; i++) s += red[i];
        atomicAdd(out, s * (1.0f / 67108864.0f));   // / (B*NE*E)
    }
}

extern "C" void kernel_launch(void* const* d_in, const int* in_sizes, int n_in,
                              void* d_out, int out_size) {
    (void)in_sizes; (void)n_in; (void)out_size;
    const float* feat = (const float*)d_in[0];
    const float* tgt  = (const float*)d_in[1];
    const float* W1   = (const float*)d_in[2];
    const float* b1   = (const float*)d_in[3];
    const float* W2   = (const float*)d_in[4];
    const float* b2   = (const float*)d_in[5];

    cudaFuncSetAttribute(distill_kernel,
                         cudaFuncAttributeMaxDynamicSharedMemorySize, SMEM_TOTAL);
    init_out_kernel<<<1, 1>>>((float*)d_out);
    dim3 grid(NE, GROUPS);
    distill_kernel<<<grid, 256, SMEM_TOTAL>>>(feat, tgt, W1, b1, W2, b2,
                                              (float*)d_out);
}